// round 2
// baseline (speedup 1.0000x reference)
#include <cuda_runtime.h>

// ---------------------------------------------------------------------------
// Threshold_weights7: per-row top-2 margins over 8 predictors [N,128],
// softmax(margins/2) over the 8 predictors, plus global max of predictors 0..6.
// Memory-bound: 512MB read. One warp per row, float4 loads, butterfly top-2.
// ---------------------------------------------------------------------------

static constexpr int kC = 128;  // class dim

__device__ unsigned g_max_key;

__device__ __forceinline__ unsigned f2key(float f) {
    // order-preserving float -> unsigned key (for atomicMax)
    unsigned u = __float_as_uint(f);
    return (u & 0x80000000u) ? ~u : (u | 0x80000000u);
}

__global__ void k_init() { g_max_key = 0u; }

__global__ void k_fin(float* __restrict__ out) {
    unsigned k = g_max_key;
    unsigned u = (k & 0x80000000u) ? (k & 0x7FFFFFFFu) : ~k;
    out[0] = __uint_as_float(u);
}

__global__ void __launch_bounds__(256)
k_main(const float* __restrict__ p0, const float* __restrict__ p1,
       const float* __restrict__ p2, const float* __restrict__ p3,
       const float* __restrict__ p4, const float* __restrict__ p5,
       const float* __restrict__ p6, const float* __restrict__ p7,
       const int* __restrict__ targets,
       float* __restrict__ thr,   // [N, 8] output (already offset-adjusted)
       int nrows)
{
    __shared__ unsigned s_gm[8];

    const int lane = threadIdx.x & 31;
    const int wib  = threadIdx.x >> 5;                    // warp in block (0..7)
    const int gwarp  = blockIdx.x * 8 + wib;
    const int nwarps = gridDim.x * 8;

    const float* preds[8] = {p0, p1, p2, p3, p4, p5, p6, p7};

    float gm = -3.402823466e38f;  // running max over predictors 0..6 (uniform per warp)

    for (int row = gwarp; row < nrows; row += nwarps) {
        const int t     = __ldg(targets + row);
        const int tlane = t >> 2;
        const int tsub  = t & 3;
        const size_t base = (size_t)row * kC + lane * 4;

        // Load all 8 rows up front: 8 independent LDG.128 per lane (MLP).
        float4 v[8];
#pragma unroll
        for (int p = 0; p < 8; p++)
            v[p] = *reinterpret_cast<const float4*>(preds[p] + base);

        float m[8];
#pragma unroll
        for (int p = 0; p < 8; p++) {
            const float4 q = v[p];
            // lane-local top-2 of 4 values
            float a1 = fmaxf(q.x, q.y), a2 = fminf(q.x, q.y);
            float b1 = fmaxf(q.z, q.w), b2 = fminf(q.z, q.w);
            float m1 = fmaxf(a1, b1);
            float m2 = fmaxf(fminf(a1, b1), fmaxf(a2, b2));

            // target logit: element (t&3) from lane (t>>2)
            float tl = (tsub == 0) ? q.x : (tsub == 1) ? q.y
                     : (tsub == 2) ? q.z : q.w;
            float tv = __shfl_sync(0xffffffffu, tl, tlane);

            // warp-wide top-2 merge (butterfly)
#pragma unroll
            for (int off = 16; off; off >>= 1) {
                float o1 = __shfl_xor_sync(0xffffffffu, m1, off);
                float o2 = __shfl_xor_sync(0xffffffffu, m2, off);
                float n2 = fmaxf(fminf(m1, o1), fmaxf(m2, o2));
                m1 = fmaxf(m1, o1);
                m2 = n2;
            }
            // margin: exact-equality semantics of the reference
            m[p] = (tv == m1) ? (m1 - m2) : 0.0f;
            if (p < 7) gm = fmaxf(gm, m1);   // m1 is the exact row max
        }

        // softmax over the 8 margins with T=2 (redundant on all lanes; cheap)
        float mm = m[0];
#pragma unroll
        for (int p = 1; p < 8; p++) mm = fmaxf(mm, m[p]);
        float e[8], s = 0.0f;
#pragma unroll
        for (int p = 0; p < 8; p++) { e[p] = __expf((m[p] - mm) * 0.5f); s += e[p]; }
        const float inv = 1.0f / s;

        if (lane < 8) {
            // select e[lane] without dynamic register indexing
            float mine = (lane == 0) ? e[0] : (lane == 1) ? e[1]
                       : (lane == 2) ? e[2] : (lane == 3) ? e[3]
                       : (lane == 4) ? e[4] : (lane == 5) ? e[5]
                       : (lane == 6) ? e[6] : e[7];
            thr[(size_t)row * 8 + lane] = mine * inv;
        }
    }

    // block-level reduce of the global max; one atomic per block
    if (lane == 0) s_gm[wib] = f2key(gm);
    __syncthreads();
    if (threadIdx.x == 0) {
        unsigned k = s_gm[0];
#pragma unroll
        for (int i = 1; i < 8; i++) k = max(k, s_gm[i]);
        atomicMax(&g_max_key, k);
    }
}

extern "C" void kernel_launch(void* const* d_in, const int* in_sizes, int n_in,
                              void* d_out, int out_size)
{
    const float* p[8];
    for (int i = 0; i < 8; i++) p[i] = (const float*)d_in[i];
    const int* targets = (const int*)d_in[8];
    const int nrows = in_sizes[8];            // targets element count == N

    float* out = (float*)d_out;
    const int off = out_size - nrows * 8;     // scalar max_preds lives before thr
    float* thr = out + (off > 0 ? off : 0);

    k_init<<<1, 1>>>();
    k_main<<<2048, 256>>>(p[0], p[1], p[2], p[3], p[4], p[5], p[6], p[7],
                          targets, thr, nrows);
    if (off >= 1) k_fin<<<1, 1>>>(out);
}

// round 4
// speedup vs baseline: 1.0878x; 1.0878x over previous
#include <cuda_runtime.h>

// ---------------------------------------------------------------------------
// Threshold_weights7: per-row top-2 margins over 8 predictors [N,128],
// softmax(margins/2) over 8 predictors, plus global max of predictors 0..6.
// Memory-bound: 512MB read. TWO rows per warp (16 lanes each), float4 x2
// loads, 4-step half-warp butterflies; single kernel, last-block finalize.
// ---------------------------------------------------------------------------

static constexpr int kC = 128;  // class dim

__device__ unsigned g_max_key;  // zero-init at load; self-reset every call
__device__ unsigned g_ticket;

__device__ __forceinline__ unsigned f2key(float f) {
    unsigned u = __float_as_uint(f);
    return (u & 0x80000000u) ? ~u : (u | 0x80000000u);
}

__global__ void __launch_bounds__(256)
k_main(const float* __restrict__ p0, const float* __restrict__ p1,
       const float* __restrict__ p2, const float* __restrict__ p3,
       const float* __restrict__ p4, const float* __restrict__ p5,
       const float* __restrict__ p6, const float* __restrict__ p7,
       const int* __restrict__ targets,
       float* __restrict__ out,   // [has_scalar + N*8]
       int nrows, int has_scalar)
{
    __shared__ unsigned s_gm[8];

    const int lane = threadIdx.x & 31;
    const int wib  = threadIdx.x >> 5;              // warp in block (0..7)
    const int half = lane >> 4;                     // 0: row A, 1: row B
    const int hl   = lane & 15;                     // lane within half
    const unsigned halfmask = 0xFFFFu << (half * 16);

    const int gwarp  = blockIdx.x * 8 + wib;
    const int nwarps = gridDim.x * 8;

    float* __restrict__ thr = out + has_scalar;
    const float* preds[8] = {p0, p1, p2, p3, p4, p5, p6, p7};

    float gm = -3.402823466e38f;   // running max over predictors 0..6

    const int npairs = (nrows + 1) >> 1;
    for (int pair = gwarp; pair < npairs; pair += nwarps) {
        const int row = pair * 2 + half;
        const bool rowok = (row < nrows);
        const int rsafe = rowok ? row : (nrows - 1);

        const int t = __ldg(targets + rsafe);
        // this row's 128 values live across 16 lanes, 8 floats each
        const int towner = t >> 3;       // lane-in-half holding the target
        const int tq     = (t >> 2) & 1; // which float4
        const int tsub   = t & 3;        // element within float4

        const size_t base = (size_t)rsafe * kC + hl * 8;

        // 16 independent LDG.128 up front (streaming: data read once).
        float4 va[8], vb[8];
#pragma unroll
        for (int p = 0; p < 8; p++) {
            va[p] = __ldcs(reinterpret_cast<const float4*>(preds[p] + base));
            vb[p] = __ldcs(reinterpret_cast<const float4*>(preds[p] + base + 4));
        }

        float m[8];
#pragma unroll
        for (int p = 0; p < 8; p++) {
            const float4 qa = va[p], qb = vb[p];
            // lane-local top-2 of 8 values
            float a1 = fmaxf(qa.x, qa.y), a2 = fminf(qa.x, qa.y);
            float b1 = fmaxf(qa.z, qa.w), b2 = fminf(qa.z, qa.w);
            float m1a = fmaxf(a1, b1);
            float m2a = fmaxf(fminf(a1, b1), fmaxf(a2, b2));
            float c1 = fmaxf(qb.x, qb.y), c2 = fminf(qb.x, qb.y);
            float d1 = fmaxf(qb.z, qb.w), d2 = fminf(qb.z, qb.w);
            float m1b = fmaxf(c1, d1);
            float m2b = fmaxf(fminf(c1, d1), fmaxf(c2, d2));
            float m1 = fmaxf(m1a, m1b);
            float m2 = fmaxf(fminf(m1a, m1b), fmaxf(m2a, m2b));

            // target logit: pick element tsub of float4 tq, from lane towner
            float ta = (tsub == 0) ? qa.x : (tsub == 1) ? qa.y
                     : (tsub == 2) ? qa.z : qa.w;
            float tb = (tsub == 0) ? qb.x : (tsub == 1) ? qb.y
                     : (tsub == 2) ? qb.z : qb.w;
            float tl = tq ? tb : ta;
            float tv = __shfl_sync(0xffffffffu, tl, towner, 16); // within half

            // 4-step butterfly top-2 merge within the 16-lane half
#pragma unroll
            for (int off = 8; off; off >>= 1) {
                float o1 = __shfl_xor_sync(0xffffffffu, m1, off);
                float o2 = __shfl_xor_sync(0xffffffffu, m2, off);
                float n2 = fmaxf(fminf(m1, o1), fmaxf(m2, o2));
                m1 = fmaxf(m1, o1);
                m2 = n2;
            }
            // margin: exact-equality tie semantics of the reference
            m[p] = (tv == m1) ? (m1 - m2) : 0.0f;
            if (p < 7 && rowok) gm = fmaxf(gm, m1);  // m1 == exact row max
        }

        // softmax over the 8 margins, T=2 (redundant across the half; cheap)
        float mm = m[0];
#pragma unroll
        for (int p = 1; p < 8; p++) mm = fmaxf(mm, m[p]);
        float e[8], s = 0.0f;
#pragma unroll
        for (int p = 0; p < 8; p++) { e[p] = __expf((m[p] - mm) * 0.5f); s += e[p]; }
        const float inv = 1.0f / s;

        if (hl < 8 && rowok) {
            float mine = (hl == 0) ? e[0] : (hl == 1) ? e[1]
                       : (hl == 2) ? e[2] : (hl == 3) ? e[3]
                       : (hl == 4) ? e[4] : (hl == 5) ? e[5]
                       : (hl == 6) ? e[6] : e[7];
            thr[(size_t)row * 8 + hl] = mine * inv;
        }
    }

    // ---- global-max finalize in the same kernel (last-block ticket) ----
    gm = fmaxf(gm, __shfl_xor_sync(0xffffffffu, gm, 16));  // merge both halves
    if (lane == 0) s_gm[wib] = f2key(gm);
    __syncthreads();
    if (threadIdx.x == 0) {
        unsigned k = s_gm[0];
#pragma unroll
        for (int i = 1; i < 8; i++) k = max(k, s_gm[i]);
        atomicMax(&g_max_key, k);
        __threadfence();
        unsigned old = atomicAdd(&g_ticket, 1u);
        if (old == gridDim.x - 1) {
            unsigned kk = g_max_key;
            if (has_scalar) {
                unsigned u = (kk & 0x80000000u) ? (kk & 0x7FFFFFFFu) : ~kk;
                out[0] = __uint_as_float(u);
            }
            g_max_key = 0u;   // reset for next graph replay
            g_ticket  = 0u;
        }
    }
}

extern "C" void kernel_launch(void* const* d_in, const int* in_sizes, int n_in,
                              void* d_out, int out_size)
{
    const float* p[8];
    for (int i = 0; i < 8; i++) p[i] = (const float*)d_in[i];
    const int* targets = (const int*)d_in[8];
    const int nrows = in_sizes[8];           // targets element count == N

    float* out = (float*)d_out;
    int has_scalar = out_size - nrows * 8;
    if (has_scalar < 0) has_scalar = 0;

    k_main<<<2048, 256>>>(p[0], p[1], p[2], p[3], p[4], p[5], p[6], p[7],
                          targets, out, nrows, has_scalar);
}

// round 5
// speedup vs baseline: 1.1103x; 1.0206x over previous
#include <cuda_runtime.h>

// ---------------------------------------------------------------------------
// Threshold_weights7: per-row top-2 margins over 8 predictors [N,128],
// softmax(margins/2) over 8 predictors, plus global max of predictors 0..6.
// Memory-bound: 512MB read. TWO rows per warp (16 lanes each); predictors in
// 2 batches of 4 to halve register pressure -> 4 blocks/SM; single kernel,
// last-block finalize.
// ---------------------------------------------------------------------------

static constexpr int kC = 128;  // class dim

__device__ unsigned g_max_key;  // zero-init at load; self-reset every call
__device__ unsigned g_ticket;

__device__ __forceinline__ unsigned f2key(float f) {
    unsigned u = __float_as_uint(f);
    return (u & 0x80000000u) ? ~u : (u | 0x80000000u);
}

__global__ void __launch_bounds__(256, 4)
k_main(const float* __restrict__ p0, const float* __restrict__ p1,
       const float* __restrict__ p2, const float* __restrict__ p3,
       const float* __restrict__ p4, const float* __restrict__ p5,
       const float* __restrict__ p6, const float* __restrict__ p7,
       const int* __restrict__ targets,
       float* __restrict__ out,   // [has_scalar + N*8]
       int nrows, int has_scalar)
{
    __shared__ unsigned s_gm[8];

    const int lane = threadIdx.x & 31;
    const int wib  = threadIdx.x >> 5;              // warp in block (0..7)
    const int half = lane >> 4;                     // 0: row A, 1: row B
    const int hl   = lane & 15;                     // lane within half

    const int gwarp  = blockIdx.x * 8 + wib;
    const int nwarps = gridDim.x * 8;

    float* __restrict__ thr = out + has_scalar;
    const float* preds[8] = {p0, p1, p2, p3, p4, p5, p6, p7};

    float gm = -3.402823466e38f;   // running max over predictors 0..6

    const int npairs = (nrows + 1) >> 1;
    for (int pair = gwarp; pair < npairs; pair += nwarps) {
        const int row = pair * 2 + half;
        const bool rowok = (row < nrows);
        const int rsafe = rowok ? row : (nrows - 1);

        const int t = __ldg(targets + rsafe);
        const int towner = t >> 3;       // lane-in-half holding the target
        const int tq     = (t >> 2) & 1; // which float4
        const int tsub   = t & 3;        // element within float4

        const size_t base = (size_t)rsafe * kC + hl * 8;

        float m[8];

        // Two batches of 4 predictors: 8 LDG.128 in flight per batch,
        // 32 data regs instead of 64 -> 4 blocks/SM.
#pragma unroll
        for (int b = 0; b < 2; b++) {
            float4 va[4], vb[4];
#pragma unroll
            for (int p = 0; p < 4; p++) {
                const float* pr = preds[b * 4 + p];
                va[p] = __ldcs(reinterpret_cast<const float4*>(pr + base));
                vb[p] = __ldcs(reinterpret_cast<const float4*>(pr + base + 4));
            }

#pragma unroll
            for (int p = 0; p < 4; p++) {
                const float4 qa = va[p], qb = vb[p];
                // lane-local top-2 of 8 values
                float a1 = fmaxf(qa.x, qa.y), a2 = fminf(qa.x, qa.y);
                float b1 = fmaxf(qa.z, qa.w), b2 = fminf(qa.z, qa.w);
                float m1a = fmaxf(a1, b1);
                float m2a = fmaxf(fminf(a1, b1), fmaxf(a2, b2));
                float c1 = fmaxf(qb.x, qb.y), c2 = fminf(qb.x, qb.y);
                float d1 = fmaxf(qb.z, qb.w), d2 = fminf(qb.z, qb.w);
                float m1b = fmaxf(c1, d1);
                float m2b = fmaxf(fminf(c1, d1), fmaxf(c2, d2));
                float m1 = fmaxf(m1a, m1b);
                float m2 = fmaxf(fminf(m1a, m1b), fmaxf(m2a, m2b));

                // target logit: element tsub of float4 tq from lane towner
                float ta = (tsub == 0) ? qa.x : (tsub == 1) ? qa.y
                         : (tsub == 2) ? qa.z : qa.w;
                float tb = (tsub == 0) ? qb.x : (tsub == 1) ? qb.y
                         : (tsub == 2) ? qb.z : qb.w;
                float tl = tq ? tb : ta;
                float tv = __shfl_sync(0xffffffffu, tl, towner, 16);

                // 4-step butterfly top-2 merge within the 16-lane half
#pragma unroll
                for (int off = 8; off; off >>= 1) {
                    float o1 = __shfl_xor_sync(0xffffffffu, m1, off);
                    float o2 = __shfl_xor_sync(0xffffffffu, m2, off);
                    float n2 = fmaxf(fminf(m1, o1), fmaxf(m2, o2));
                    m1 = fmaxf(m1, o1);
                    m2 = n2;
                }
                // margin: exact-equality tie semantics of the reference
                m[b * 4 + p] = (tv == m1) ? (m1 - m2) : 0.0f;
                if ((b * 4 + p) < 7 && rowok) gm = fmaxf(gm, m1);
            }
        }

        // softmax over the 8 margins, T=2 (redundant across the half; cheap)
        float mm = m[0];
#pragma unroll
        for (int p = 1; p < 8; p++) mm = fmaxf(mm, m[p]);
        float e[8], s = 0.0f;
#pragma unroll
        for (int p = 0; p < 8; p++) { e[p] = __expf((m[p] - mm) * 0.5f); s += e[p]; }
        const float inv = 1.0f / s;

        if (hl < 8 && rowok) {
            float mine = (hl == 0) ? e[0] : (hl == 1) ? e[1]
                       : (hl == 2) ? e[2] : (hl == 3) ? e[3]
                       : (hl == 4) ? e[4] : (hl == 5) ? e[5]
                       : (hl == 6) ? e[6] : e[7];
            thr[(size_t)row * 8 + hl] = mine * inv;
        }
    }

    // ---- global-max finalize in the same kernel (last-block ticket) ----
    gm = fmaxf(gm, __shfl_xor_sync(0xffffffffu, gm, 16));  // merge both halves
    if (lane == 0) s_gm[wib] = f2key(gm);
    __syncthreads();
    if (threadIdx.x == 0) {
        unsigned k = s_gm[0];
#pragma unroll
        for (int i = 1; i < 8; i++) k = max(k, s_gm[i]);
        atomicMax(&g_max_key, k);
        __threadfence();
        unsigned old = atomicAdd(&g_ticket, 1u);
        if (old == gridDim.x - 1) {
            unsigned kk = g_max_key;
            if (has_scalar) {
                unsigned u = (kk & 0x80000000u) ? (kk & 0x7FFFFFFFu) : ~kk;
                out[0] = __uint_as_float(u);
            }
            g_max_key = 0u;   // reset for next graph replay
            g_ticket  = 0u;
        }
    }
}

extern "C" void kernel_launch(void* const* d_in, const int* in_sizes, int n_in,
                              void* d_out, int out_size)
{
    const float* p[8];
    for (int i = 0; i < 8; i++) p[i] = (const float*)d_in[i];
    const int* targets = (const int*)d_in[8];
    const int nrows = in_sizes[8];           // targets element count == N

    float* out = (float*)d_out;
    int has_scalar = out_size - nrows * 8;
    if (has_scalar < 0) has_scalar = 0;

    k_main<<<2048, 256>>>(p[0], p[1], p[2], p[3], p[4], p[5], p[6], p[7],
                          targets, out, nrows, has_scalar);
}